// round 12
// baseline (speedup 1.0000x reference)
#include <cuda_runtime.h>
#include <cuda_fp16.h>

// ---- problem constants ----
#define Bb   32      // batch
#define Ii   32      // input capsules
#define AIN  16      // input atoms
#define OD   10      // output classes
#define OA   16      // output atoms
#define HWp  144     // 12*12 spatial
#define Kk   160     // OD*OA
#define NPOS (Bb*HWp)   // 4608 positions
#define NCHUNK 4     // pipeline chunks (8 batches each)

// votes scratch in fp16, layout [pos][d][i][a]  (47.2 MB)
__device__ __half g_votesh[(size_t)NPOS * Ii * Kk];

// ============================================================================
// Kernel A (R11, + block offset): votes for one (b,i). 160 threads, t=d*16+a.
// ============================================================================
__global__ void __launch_bounds__(160) votes_kernel(const float* __restrict__ x,
                                                    const float* __restrict__ w,
                                                    int bi0)
{
    const int bi = blockIdx.x + bi0;  // b*32 + i
    const int b  = bi >> 5;
    const int i  = bi & 31;
    const int t  = threadIdx.x;       // 0..159 == d*16+a

    __shared__ __align__(16) float xs[AIN * HWp];   // 9 KB

    const float* xg = x + (size_t)bi * (AIN * HWp);
    for (int idx = t; idx < AIN * HWp; idx += 160) xs[idx] = xg[idx];

    float wr[AIN];
#pragma unroll
    for (int ai = 0; ai < AIN; ai++)
        wr[ai] = w[(i * AIN + ai) * Kk + t];

    __syncthreads();

    __half* vbase = g_votesh + (size_t)(b * HWp) * (Ii * Kk)
                  + (size_t)((t >> 4) * (Ii * OA) + i * OA + (t & 15));

#pragma unroll 2
    for (int h8 = 0; h8 < HWp / 8; h8++) {
        float4 acc0 = make_float4(0.f, 0.f, 0.f, 0.f);
        float4 acc1 = make_float4(0.f, 0.f, 0.f, 0.f);
#pragma unroll
        for (int ai = 0; ai < AIN; ai++) {
            const float4 xv0 = *(const float4*)(xs + ai * HWp + h8 * 8);
            const float4 xv1 = *(const float4*)(xs + ai * HWp + h8 * 8 + 4);
            acc0.x = fmaf(wr[ai], xv0.x, acc0.x);
            acc0.y = fmaf(wr[ai], xv0.y, acc0.y);
            acc0.z = fmaf(wr[ai], xv0.z, acc0.z);
            acc0.w = fmaf(wr[ai], xv0.w, acc0.w);
            acc1.x = fmaf(wr[ai], xv1.x, acc1.x);
            acc1.y = fmaf(wr[ai], xv1.y, acc1.y);
            acc1.z = fmaf(wr[ai], xv1.z, acc1.z);
            acc1.w = fmaf(wr[ai], xv1.w, acc1.w);
        }
        __half* p = vbase + (size_t)(h8 * 8) * (Ii * Kk);
        p[0]               = __float2half_rn(acc0.x);
        p[Ii * Kk]         = __float2half_rn(acc0.y);
        p[2 * (Ii * Kk)]   = __float2half_rn(acc0.z);
        p[3 * (Ii * Kk)]   = __float2half_rn(acc0.w);
        p[4 * (Ii * Kk)]   = __float2half_rn(acc1.x);
        p[5 * (Ii * Kk)]   = __float2half_rn(acc1.y);
        p[6 * (Ii * Kk)]   = __float2half_rn(acc1.z);
        p[7 * (Ii * Kk)]   = __float2half_rn(acc1.w);
    }
}

// ============================================================================
// Kernel B (R11, + block offset): routing, 2 positions per block sequential,
// 10 warps, launch_bounds (320,4) -> 48 regs, 4 blocks/SM.
// ============================================================================
__global__ void __launch_bounds__(320, 4) route_kernel(const float* __restrict__ bias,
                                                       float* __restrict__ out,
                                                       int blk0)
{
    const int pos0 = (blockIdx.x + blk0) * 2;   // pos0, pos0+1 share batch b
    const int d    = threadIdx.x >> 5;
    const int lane = threadIdx.x & 31;
    const int i16  = lane & 15;
    const int grp  = lane >> 4;

    __shared__ float2 ex2[2][OD][16];

    const __half* vb = g_votesh + (size_t)pos0 * (Ii * Kk)
                     + d * (Ii * OA) + (i16 * 2) * OA + grp * 8;
    uint4 raw[4];
    raw[0] = *(const uint4*)(vb);
    raw[1] = *(const uint4*)(vb + OA);
    raw[2] = *(const uint4*)(vb + Ii * Kk);
    raw[3] = *(const uint4*)(vb + Ii * Kk + OA);

    const int atom = grp * 8 + ((lane >> 1) & 7);
    const float bv = bias[d * OA + atom];
    const int b   = pos0 / HWp;
    const int hw0 = pos0 - b * HWp;
    const unsigned FULL = 0xffffffffu;

#pragma unroll
    for (int p = 0; p < 2; p++) {
        float va0[8], va1[8];
        {
            const __half2* h0 = (const __half2*)&raw[2 * p];
            const __half2* h1 = (const __half2*)&raw[2 * p + 1];
#pragma unroll
            for (int k = 0; k < 4; k++) {
                float2 f0 = __half22float2(h0[k]);
                float2 f1 = __half22float2(h1[k]);
                va0[2 * k] = f0.x; va0[2 * k + 1] = f0.y;
                va1[2 * k] = f1.x; va1[2 * k + 1] = f1.y;
            }
        }

        float logitA = 0.f, logitB = 0.f;
        float outP = 0.f, outScale = 0.f;

#pragma unroll
        for (int r = 0; r < 3; r++) {
            float routeA, routeB;
            if (r == 0) {
                routeA = routeB = 0.1f;
            } else {
                float e0 = __expf(logitA), e1 = __expf(logitB);
                if (grp == 0) ex2[r - 1][d][i16] = make_float2(e0, e1);
                __syncthreads();
                float sA = 0.f, sB = 0.f;
#pragma unroll
                for (int d2 = 0; d2 < OD; d2++) {
                    float2 v = ex2[r - 1][d2][i16];
                    sA += v.x; sB += v.y;
                }
                routeA = __fdividef(e0, sA);
                routeB = __fdividef(e1, sB);
            }

            float q[8];
#pragma unroll
            for (int k = 0; k < 8; k++)
                q[k] = fmaf(routeB, va1[k], routeA * va0[k]);

            {
                const bool hi = (lane & 8) != 0;
#pragma unroll
                for (int k = 0; k < 4; k++) {
                    float snd = hi ? q[k] : q[k + 4];
                    float rcv = __shfl_xor_sync(FULL, snd, 8);
                    q[k] = (hi ? q[k + 4] : q[k]) + rcv;
                }
            }
            {
                const bool hi = (lane & 4) != 0;
#pragma unroll
                for (int k = 0; k < 2; k++) {
                    float snd = hi ? q[k] : q[k + 2];
                    float rcv = __shfl_xor_sync(FULL, snd, 4);
                    q[k] = (hi ? q[k + 2] : q[k]) + rcv;
                }
            }
            float s;
            {
                const bool hi = (lane & 2) != 0;
                float snd = hi ? q[0] : q[1];
                float rcv = __shfl_xor_sync(FULL, snd, 2);
                s = (hi ? q[1] : q[0]) + rcv;
            }
            s += __shfl_xor_sync(FULL, s, 1);

            const float P = s + bv;

            if (r < 2) {
                float act[8];
#pragma unroll
                for (int k = 0; k < 8; k++)
                    act[k] = __shfl_sync(FULL, P, (lane & 16) | (k << 1));

                float n2p = 0.f;
#pragma unroll
                for (int k = 0; k < 8; k++) n2p = fmaf(act[k], act[k], n2p);
                float n2 = n2p + __shfl_xor_sync(FULL, n2p, 16);
                float scale = __fdividef(sqrtf(n2), 1.f + n2);

                float dA = 0.f, dB = 0.f;
#pragma unroll
                for (int k = 0; k < 8; k++) {
                    dA = fmaf(va0[k], act[k], dA);
                    dB = fmaf(va1[k], act[k], dB);
                }
                dA += __shfl_xor_sync(FULL, dA, 16);
                dB += __shfl_xor_sync(FULL, dB, 16);
                logitA = fmaf(dA, scale, logitA);
                logitB = fmaf(dB, scale, logitB);
            } else {
                float sq = P * P;
#pragma unroll
                for (int off = 16; off; off >>= 1)
                    sq += __shfl_xor_sync(FULL, sq, off);
                float n2 = 0.5f * sq;
                outScale = __fdividef(sqrtf(n2), 1.f + n2);
                outP = P;
            }
        }

        if ((lane & 1) == 0) {
            out[((size_t)(b * OD + d) * OA + atom) * HWp + hw0 + p] = outP * outScale;
        }
    }
}

// ============================================================================
// Launch: 4-chunk pipeline. Stream 0 (captured) runs votes chunks; forked
// stream runs route chunks gated on per-chunk events. Join at the end.
// Streams/events are created fresh per call (host code runs only during
// correctness + capture; graph replays re-execute only the captured nodes).
// ============================================================================
extern "C" void kernel_launch(void* const* d_in, const int* in_sizes, int n_in,
                              void* d_out, int out_size)
{
    const float* x    = (const float*)d_in[0];   // [32,32,16,12,12]
    const float* w    = (const float*)d_in[1];   // [32,16,160]
    const float* bias = (const float*)d_in[2];   // [10,16,1,1]
    float* out = (float*)d_out;                  // [32,10,16,12,12]

    cudaStream_t s2;
    cudaStreamCreateWithFlags(&s2, cudaStreamNonBlocking);

    const int vblk = (Bb * Ii) / NCHUNK;    // 256 votes blocks per chunk
    const int rblk = (NPOS / 2) / NCHUNK;   // 576 route blocks per chunk

    cudaEvent_t evJoin;
    cudaEventCreateWithFlags(&evJoin, cudaEventDisableTiming);

    for (int c = 0; c < NCHUNK; c++) {
        votes_kernel<<<vblk, 160, 0, 0>>>(x, w, c * vblk);

        cudaEvent_t ev;
        cudaEventCreateWithFlags(&ev, cudaEventDisableTiming);
        cudaEventRecord(ev, 0);             // after votes chunk c
        cudaStreamWaitEvent(s2, ev, 0);     // fork: route chunk c gated on it

        route_kernel<<<rblk, 320, 0, s2>>>(bias, out, c * rblk);
    }

    cudaEventRecord(evJoin, s2);
    cudaStreamWaitEvent(0, evJoin, 0);      // join back into captured stream
}

// round 14
// speedup vs baseline: 2.1397x; 2.1397x over previous
#include <cuda_runtime.h>
#include <cuda_fp16.h>

// ---- problem constants ----
#define Bb   32      // batch
#define Ii   32      // input capsules
#define AIN  16      // input atoms
#define OD   10      // output classes
#define OA   16      // output atoms
#define HWp  144     // 12*12 spatial
#define Kk   160     // OD*OA
#define NPOS (Bb*HWp)   // 4608 positions
#define NPAIR (NPOS/2)  // 2304 position pairs
#define PSTR (Ii*Kk)    // 5120 half2 per pair

// votes scratch: [pair][d][i][a], element half2 = (pos_even, pos_odd). 47.2 MB.
__device__ __half2 g_v2[(size_t)NPAIR * PSTR];

// ============================================================================
// Kernel A: votes for one (b,i). 160 threads, t = d*16+a.
// 8 positions per iter -> 4 half2 stores (64B-coalesced per half-warp).
// ============================================================================
__global__ void __launch_bounds__(160) votes_kernel(const float* __restrict__ x,
                                                    const float* __restrict__ w)
{
    const int bi = blockIdx.x;        // b*32 + i
    const int b  = bi >> 5;
    const int i  = bi & 31;
    const int t  = threadIdx.x;       // 0..159 == d*16+a

    __shared__ __align__(16) float xs[AIN * HWp];   // 9 KB

    const float* xg = x + (size_t)bi * (AIN * HWp);
    for (int idx = t; idx < AIN * HWp; idx += 160) xs[idx] = xg[idx];

    float wr[AIN];
#pragma unroll
    for (int ai = 0; ai < AIN; ai++)
        wr[ai] = w[(i * AIN + ai) * Kk + t];

    __syncthreads();

    // block's pairs start at b*72; element offset (d, i, a)
    __half2* vbase = g_v2 + (size_t)(b * (HWp / 2)) * PSTR
                   + (size_t)((t >> 4) * (Ii * OA) + i * OA + (t & 15));

#pragma unroll 2
    for (int h8 = 0; h8 < HWp / 8; h8++) {          // 18 iters, pairs 4h8..4h8+3
        float4 acc0 = make_float4(0.f, 0.f, 0.f, 0.f);
        float4 acc1 = make_float4(0.f, 0.f, 0.f, 0.f);
#pragma unroll
        for (int ai = 0; ai < AIN; ai++) {
            const float4 xv0 = *(const float4*)(xs + ai * HWp + h8 * 8);
            const float4 xv1 = *(const float4*)(xs + ai * HWp + h8 * 8 + 4);
            acc0.x = fmaf(wr[ai], xv0.x, acc0.x);
            acc0.y = fmaf(wr[ai], xv0.y, acc0.y);
            acc0.z = fmaf(wr[ai], xv0.z, acc0.z);
            acc0.w = fmaf(wr[ai], xv0.w, acc0.w);
            acc1.x = fmaf(wr[ai], xv1.x, acc1.x);
            acc1.y = fmaf(wr[ai], xv1.y, acc1.y);
            acc1.z = fmaf(wr[ai], xv1.z, acc1.z);
            acc1.w = fmaf(wr[ai], xv1.w, acc1.w);
        }
        __half2* p = vbase + (size_t)(4 * h8) * PSTR;
        p[0]        = __floats2half2_rn(acc0.x, acc0.y);   // pair 4h8
        p[PSTR]     = __floats2half2_rn(acc0.z, acc0.w);   // pair 4h8+1
        p[2 * PSTR] = __floats2half2_rn(acc1.x, acc1.y);   // pair 4h8+2
        p[3 * PSTR] = __floats2half2_rn(acc1.z, acc1.w);   // pair 4h8+3
    }
}

// ============================================================================
// Kernel B: routing (R11 structure). One block per position pair; 10 warps
// (warp = class d); positions sequential. 4 up-front LDG.128: 8 atoms x
// half2 = 32B per capsule = TWO uint4 per capsule (the R13 bug was one).
// launch_bounds (320,4) -> 48 regs, 4 blocks/SM.
// ============================================================================
__global__ void __launch_bounds__(320, 4) route_kernel(const float* __restrict__ bias,
                                                       float* __restrict__ out)
{
    const int pair = blockIdx.x;            // positions 2*pair, 2*pair+1
    const int d    = threadIdx.x >> 5;      // warp id = class
    const int lane = threadIdx.x & 31;
    const int i16  = lane & 15;             // capsule pair index
    const int grp  = lane >> 4;             // atom group

    __shared__ float2 ex2[2][OD][16];       // exp(logit) pairs per softmax round

    // ---- 4 loads: 2 per capsule (8 atoms x 4B half2 = 32B each) ----
    const __half2* vb = g_v2 + (size_t)pair * PSTR
                      + d * (Ii * OA) + (i16 * 2) * OA + grp * 8;
    uint4 rawA[2], rawB[2];
    rawA[0] = *(const uint4*)(vb);            // capsule 2*i16,   atoms grp*8+0..3
    rawA[1] = *(const uint4*)(vb + 4);        // capsule 2*i16,   atoms grp*8+4..7
    rawB[0] = *(const uint4*)(vb + OA);       // capsule 2*i16+1, atoms grp*8+0..3
    rawB[1] = *(const uint4*)(vb + OA + 4);   // capsule 2*i16+1, atoms grp*8+4..7

    const int atom = grp * 8 + ((lane >> 1) & 7);   // atom this lane owns post-reduce
    const float bv = bias[d * OA + atom];
    const int b   = (2 * pair) / HWp;
    const int hw0 = 2 * pair - b * HWp;
    const unsigned FULL = 0xffffffffu;

#pragma unroll
    for (int p = 0; p < 2; p++) {
        // ---- unpack this position's votes (.x of half2 for p=0, .y for p=1) ----
        float va0[8], va1[8];
        {
            const __half2* hA = (const __half2*)rawA;   // 8 contiguous half2
            const __half2* hB = (const __half2*)rawB;
#pragma unroll
            for (int k = 0; k < 8; k++) {
                const float2 fA = __half22float2(hA[k]);
                const float2 fB = __half22float2(hB[k]);
                va0[k] = (p == 0) ? fA.x : fA.y;
                va1[k] = (p == 0) ? fB.x : fB.y;
            }
        }

        float logitA = 0.f, logitB = 0.f;
        float outP = 0.f, outScale = 0.f;

#pragma unroll
        for (int r = 0; r < 3; r++) {
            // ---- softmax over d ----
            float routeA, routeB;
            if (r == 0) {
                routeA = routeB = 0.1f;
            } else {
                float e0 = __expf(logitA), e1 = __expf(logitB);
                if (grp == 0) ex2[r - 1][d][i16] = make_float2(e0, e1);
                __syncthreads();
                float sA = 0.f, sB = 0.f;
#pragma unroll
                for (int d2 = 0; d2 < OD; d2++) {
                    float2 v = ex2[r - 1][d2][i16];
                    sA += v.x; sB += v.y;
                }
                routeA = __fdividef(e0, sA);
                routeB = __fdividef(e1, sB);
            }

            // ---- q[k] = routeA*va0[k] + routeB*va1[k] (8 own-group atoms) ----
            float q[8];
#pragma unroll
            for (int k = 0; k < 8; k++)
                q[k] = fmaf(routeB, va1[k], routeA * va0[k]);

            // ---- atom-splitting reduce over 16-lane half ----
            {
                const bool hi = (lane & 8) != 0;
#pragma unroll
                for (int k = 0; k < 4; k++) {
                    float snd = hi ? q[k] : q[k + 4];
                    float rcv = __shfl_xor_sync(FULL, snd, 8);
                    q[k] = (hi ? q[k + 4] : q[k]) + rcv;
                }
            }
            {
                const bool hi = (lane & 4) != 0;
#pragma unroll
                for (int k = 0; k < 2; k++) {
                    float snd = hi ? q[k] : q[k + 2];
                    float rcv = __shfl_xor_sync(FULL, snd, 4);
                    q[k] = (hi ? q[k + 2] : q[k]) + rcv;
                }
            }
            float s;
            {
                const bool hi = (lane & 2) != 0;
                float snd = hi ? q[0] : q[1];
                float rcv = __shfl_xor_sync(FULL, snd, 2);
                s = (hi ? q[1] : q[0]) + rcv;
            }
            s += __shfl_xor_sync(FULL, s, 1);

            const float P = s + bv;         // pre-squash preact for `atom`

            if (r < 2) {
                // ---- broadcast own-group pre-squash atoms ----
                float act[8];
#pragma unroll
                for (int k = 0; k < 8; k++)
                    act[k] = __shfl_sync(FULL, P, (lane & 16) | (k << 1));

                float n2p = 0.f;
#pragma unroll
                for (int k = 0; k < 8; k++) n2p = fmaf(act[k], act[k], n2p);
                float n2 = n2p + __shfl_xor_sync(FULL, n2p, 16);
                float scale = __fdividef(sqrtf(n2), 1.f + n2);

                float dA = 0.f, dB = 0.f;
#pragma unroll
                for (int k = 0; k < 8; k++) {
                    dA = fmaf(va0[k], act[k], dA);
                    dB = fmaf(va1[k], act[k], dB);
                }
                dA += __shfl_xor_sync(FULL, dA, 16);
                dB += __shfl_xor_sync(FULL, dB, 16);
                logitA = fmaf(dA, scale, logitA);
                logitB = fmaf(dB, scale, logitB);
            } else {
                float sq = P * P;
#pragma unroll
                for (int off = 16; off; off >>= 1)
                    sq += __shfl_xor_sync(FULL, sq, off);
                float n2 = 0.5f * sq;       // each atom counted twice
                outScale = __fdividef(sqrtf(n2), 1.f + n2);
                outP = P;
            }
        }

        // ---- output: even lane of each atom pair writes ----
        if ((lane & 1) == 0) {
            out[((size_t)(b * OD + d) * OA + atom) * HWp + hw0 + p] = outP * outScale;
        }
    }
}

extern "C" void kernel_launch(void* const* d_in, const int* in_sizes, int n_in,
                              void* d_out, int out_size)
{
    const float* x    = (const float*)d_in[0];   // [32,32,16,12,12]
    const float* w    = (const float*)d_in[1];   // [32,16,160]
    const float* bias = (const float*)d_in[2];   // [10,16,1,1]
    float* out = (float*)d_out;                  // [32,10,16,12,12]

    votes_kernel<<<Bb * Ii, 160>>>(x, w);
    route_kernel<<<NPAIR, 320>>>(bias, out);
}